// round 1
// baseline (speedup 1.0000x reference)
#include <cuda_runtime.h>
#include <cuda_bf16.h>

#define HIDDEN 2048
#define LQ 2048
#define BATCH 2
#define NQH 32
#define NKVH 8
#define HDIM 64
#define MROWS (BATCH * LQ)   // 4096

// ---------------- scratch (device globals: no allocation allowed) ----------------
__device__ float g_q[BATCH * LQ * NQH * HDIM];     // [B, L, 32, 64]
__device__ float g_k[BATCH * LQ * NKVH * HDIM];    // [B, L, 8, 64]
__device__ float g_v[BATCH * LQ * NKVH * HDIM];    // [B, L, 8, 64]
__device__ float g_attn[BATCH * LQ * NQH * HDIM];  // [B, L, 32, 64]

// ---------------- SGEMM: Y[m,n] = sum_k X[m,k] * W[n,k] + bias[n] ----------------
// X: [M,K] row-major, W: [N,K] row-major. BM=BN=64, BK=16, 256 threads, 4x4 micro.
__global__ __launch_bounds__(256) void sgemm_wt_bias(
    const float* __restrict__ X, const float* __restrict__ W,
    const float* __restrict__ bias, float* __restrict__ Y,
    int M, int N, int K)
{
    __shared__ float As[16][64];
    __shared__ float Bs[16][64];

    const int tid = threadIdx.x;
    const int bm = blockIdx.y * 64;
    const int bn = blockIdx.x * 64;
    const int tx = tid & 15;       // 0..15 -> n micro
    const int ty = tid >> 4;       // 0..15 -> m micro

    const int lrow = tid >> 2;         // 0..63
    const int lcol = (tid & 3) * 4;    // 0,4,8,12

    const float* Xp = X + (size_t)(bm + lrow) * K + lcol;
    const float* Wp = W + (size_t)(bn + lrow) * K + lcol;

    float acc[4][4];
#pragma unroll
    for (int i = 0; i < 4; i++)
#pragma unroll
        for (int j = 0; j < 4; j++) acc[i][j] = 0.0f;

    for (int k0 = 0; k0 < K; k0 += 16) {
        float4 xa = *(const float4*)(Xp + k0);
        float4 wb = *(const float4*)(Wp + k0);
        __syncthreads();
        As[lcol + 0][lrow] = xa.x;
        As[lcol + 1][lrow] = xa.y;
        As[lcol + 2][lrow] = xa.z;
        As[lcol + 3][lrow] = xa.w;
        Bs[lcol + 0][lrow] = wb.x;
        Bs[lcol + 1][lrow] = wb.y;
        Bs[lcol + 2][lrow] = wb.z;
        Bs[lcol + 3][lrow] = wb.w;
        __syncthreads();

#pragma unroll
        for (int kk = 0; kk < 16; kk++) {
            float4 a = *(const float4*)&As[kk][ty * 4];
            float4 b = *(const float4*)&Bs[kk][tx * 4];
            float av[4] = {a.x, a.y, a.z, a.w};
            float bv[4] = {b.x, b.y, b.z, b.w};
#pragma unroll
            for (int i = 0; i < 4; i++)
#pragma unroll
                for (int j = 0; j < 4; j++)
                    acc[i][j] += av[i] * bv[j];
        }
    }

    float4 bb = *(const float4*)(bias + bn + tx * 4);
    float bvv[4] = {bb.x, bb.y, bb.z, bb.w};
#pragma unroll
    for (int i = 0; i < 4; i++) {
        float4 o4;
        o4.x = acc[i][0] + bvv[0];
        o4.y = acc[i][1] + bvv[1];
        o4.z = acc[i][2] + bvv[2];
        o4.w = acc[i][3] + bvv[3];
        *(float4*)(Y + (size_t)(bm + ty * 4 + i) * N + bn + tx * 4) = o4;
    }
}

// ---------------- Flash attention (fp32, causal + key padding mask) ----------------
// grid: (L/128, 32 q-heads, B). 128 threads; thread t owns q row qb*128+t.
// KV tiles of 32 rows x 64 dims staged in smem (broadcast reads -> conflict-free).
__global__ __launch_bounds__(128) void flash_attn_kernel(
    const float* __restrict__ Q, const float* __restrict__ K,
    const float* __restrict__ V, const int* __restrict__ AM,
    float* __restrict__ O)
{
    __shared__ float Ks[32][64];
    __shared__ float Vs[32][64];
    __shared__ int   Ms[32];

    const int qb  = blockIdx.x;
    const int h   = blockIdx.y;
    const int b   = blockIdx.z;
    const int kvh = h >> 2;                 // GROUP = 4
    const int r   = qb * 128 + threadIdx.x; // my q row

    float qreg[64];
    const float* qp = Q + (((size_t)b * LQ + r) * NQH + h) * HDIM;
#pragma unroll
    for (int d = 0; d < 64; d += 4) {
        float4 t = *(const float4*)(qp + d);
        qreg[d + 0] = t.x * 0.125f;  // 1/sqrt(64)
        qreg[d + 1] = t.y * 0.125f;
        qreg[d + 2] = t.z * 0.125f;
        qreg[d + 3] = t.w * 0.125f;
    }

    float acc[64];
#pragma unroll
    for (int d = 0; d < 64; d++) acc[d] = 0.0f;
    float mrun = -1e30f, lrun = 0.0f;

    const int kend = qb * 128 + 128;   // causal: keys beyond block's last row never needed
    for (int t0 = 0; t0 < kend; t0 += 32) {
        __syncthreads();
        // stage 32 x 64 K and V rows (512 float4 each; 4 per thread)
#pragma unroll
        for (int ii = 0; ii < 4; ii++) {
            int i = threadIdx.x + ii * 128;
            int row = i >> 4;
            int c   = (i & 15) << 2;
            const size_t base = (((size_t)b * LQ + t0 + row) * NKVH + kvh) * HDIM + c;
            *(float4*)&Ks[row][c] = *(const float4*)(K + base);
            *(float4*)&Vs[row][c] = *(const float4*)(V + base);
        }
        if (threadIdx.x < 32) Ms[threadIdx.x] = AM[(size_t)b * LQ + t0 + threadIdx.x];
        __syncthreads();

        float s[32];
#pragma unroll
        for (int j = 0; j < 32; j++) {
            float s0 = 0.f, s1 = 0.f, s2 = 0.f, s3 = 0.f;
#pragma unroll
            for (int d = 0; d < 64; d += 4) {
                float4 kk = *(const float4*)&Ks[j][d];
                s0 += qreg[d + 0] * kk.x;
                s1 += qreg[d + 1] * kk.y;
                s2 += qreg[d + 2] * kk.z;
                s3 += qreg[d + 3] * kk.w;
            }
            float sv = (s0 + s1) + (s2 + s3);
            int key = t0 + j;
            s[j] = (key <= r && Ms[j] != 0) ? sv : -1e30f;
        }

        float mt = mrun;
#pragma unroll
        for (int j = 0; j < 32; j++) mt = fmaxf(mt, s[j]);
        float scale = __expf(mrun - mt);
        float psum = 0.0f;
#pragma unroll
        for (int j = 0; j < 32; j++) {
            float p = __expf(s[j] - mt);
            s[j] = p;
            psum += p;
        }
        mrun = mt;
        lrun = lrun * scale + psum;

#pragma unroll
        for (int d = 0; d < 64; d++) acc[d] *= scale;
#pragma unroll
        for (int j = 0; j < 32; j++) {
            float p = s[j];
#pragma unroll
            for (int d = 0; d < 64; d += 4) {
                float4 vv = *(const float4*)&Vs[j][d];
                acc[d + 0] += p * vv.x;
                acc[d + 1] += p * vv.y;
                acc[d + 2] += p * vv.z;
                acc[d + 3] += p * vv.w;
            }
        }
    }

    float inv = 1.0f / lrun;
    float* op = O + (((size_t)b * LQ + r) * NQH + h) * HDIM;
#pragma unroll
    for (int d = 0; d < 64; d += 4) {
        float4 o4;
        o4.x = acc[d + 0] * inv;
        o4.y = acc[d + 1] * inv;
        o4.z = acc[d + 2] * inv;
        o4.w = acc[d + 3] * inv;
        *(float4*)(op + d) = o4;
    }
}

// ---------------- launch ----------------
extern "C" void kernel_launch(void* const* d_in, const int* in_sizes, int n_in,
                              void* d_out, int out_size)
{
    const float* x   = (const float*)d_in[0];
    const int*   am  = (const int*)  d_in[1];
    const float* q_w = (const float*)d_in[2];
    const float* q_b = (const float*)d_in[3];
    const float* k_w = (const float*)d_in[4];
    const float* k_b = (const float*)d_in[5];
    const float* v_w = (const float*)d_in[6];
    const float* v_b = (const float*)d_in[7];
    const float* o_w = (const float*)d_in[8];
    const float* o_b = (const float*)d_in[9];
    float* out = (float*)d_out;

    float *gq, *gk, *gv, *ga;
    cudaGetSymbolAddress((void**)&gq, g_q);
    cudaGetSymbolAddress((void**)&gk, g_k);
    cudaGetSymbolAddress((void**)&gv, g_v);
    cudaGetSymbolAddress((void**)&ga, g_attn);

    // projections: Y = X * W^T + b
    sgemm_wt_bias<<<dim3(HIDDEN / 64, MROWS / 64), 256>>>(x, q_w, q_b, gq, MROWS, HIDDEN, HIDDEN);
    sgemm_wt_bias<<<dim3((NKVH * HDIM) / 64, MROWS / 64), 256>>>(x, k_w, k_b, gk, MROWS, NKVH * HDIM, HIDDEN);
    sgemm_wt_bias<<<dim3((NKVH * HDIM) / 64, MROWS / 64), 256>>>(x, v_w, v_b, gv, MROWS, NKVH * HDIM, HIDDEN);

    // attention
    flash_attn_kernel<<<dim3(LQ / 128, NQH, BATCH), 128>>>(gq, gk, gv, am, ga);

    // output projection
    sgemm_wt_bias<<<dim3(HIDDEN / 64, MROWS / 64), 256>>>(ga, o_w, o_b, out, MROWS, HIDDEN, HIDDEN);
}

// round 3
// speedup vs baseline: 1.7107x; 1.7107x over previous
#include <cuda_runtime.h>
#include <cuda_bf16.h>
#include <cstdint>

#define HIDDEN 2048
#define LQ 2048
#define BATCH 2
#define NQH 32
#define NKVH 8
#define HDIM 64
#define MROWS (BATCH * LQ)   // 4096
#define KVDIM (NKVH * HDIM)  // 512

// ---------------- scratch (device globals: no allocation allowed) ----------------
__device__ float g_q[MROWS * HIDDEN];
__device__ float g_k[MROWS * KVDIM];
__device__ float g_v[MROWS * KVDIM];
__device__ float g_attn[MROWS * HIDDEN];

__device__ __align__(16) __nv_bfloat16 g_xhi[MROWS * HIDDEN];
__device__ __align__(16) __nv_bfloat16 g_xlo[MROWS * HIDDEN];
__device__ __align__(16) __nv_bfloat16 g_qwhi[HIDDEN * HIDDEN];
__device__ __align__(16) __nv_bfloat16 g_qwlo[HIDDEN * HIDDEN];
__device__ __align__(16) __nv_bfloat16 g_kwhi[KVDIM * HIDDEN];
__device__ __align__(16) __nv_bfloat16 g_kwlo[KVDIM * HIDDEN];
__device__ __align__(16) __nv_bfloat16 g_vwhi[KVDIM * HIDDEN];
__device__ __align__(16) __nv_bfloat16 g_vwlo[KVDIM * HIDDEN];
__device__ __align__(16) __nv_bfloat16 g_owhi[HIDDEN * HIDDEN];
__device__ __align__(16) __nv_bfloat16 g_owlo[HIDDEN * HIDDEN];
__device__ __align__(16) __nv_bfloat16 g_ahi[MROWS * HIDDEN];
__device__ __align__(16) __nv_bfloat16 g_alo[MROWS * HIDDEN];

// ---------------- PTX helpers (base ISA only: sm_80-era) ----------------
__device__ __forceinline__ uint32_t smem_u32(const void* p) {
    uint32_t a;
    asm("{ .reg .u64 t; cvta.to.shared.u64 t, %1; cvt.u32.u64 %0, t; }" : "=r"(a) : "l"(p));
    return a;
}
__device__ __forceinline__ void cpasync16(uint32_t saddr, const void* g) {
    asm volatile("cp.async.cg.shared.global [%0], [%1], 16;" :: "r"(saddr), "l"(g) : "memory");
}
__device__ __forceinline__ void ldsm4(uint32_t* r, uint32_t addr) {
    asm volatile("ldmatrix.sync.aligned.m8n8.x4.shared.b16 {%0,%1,%2,%3}, [%4];"
        : "=r"(r[0]), "=r"(r[1]), "=r"(r[2]), "=r"(r[3]) : "r"(addr));
}
__device__ __forceinline__ void mma_bf16(float* c, const uint32_t* a, const uint32_t* b) {
    asm volatile("mma.sync.aligned.m16n8k16.row.col.f32.bf16.bf16.f32 "
        "{%0,%1,%2,%3}, {%4,%5,%6,%7}, {%8,%9}, {%0,%1,%2,%3};"
        : "+f"(c[0]), "+f"(c[1]), "+f"(c[2]), "+f"(c[3])
        : "r"(a[0]), "r"(a[1]), "r"(a[2]), "r"(a[3]), "r"(b[0]), "r"(b[1]));
}
// swizzled smem addr: 64B rows (BK=32 bf16), 16B chunk index kc (0..3)
__device__ __forceinline__ uint32_t swz(uint32_t tb, int row, int kc) {
    return tb + row * 64 + (((kc ^ ((row >> 1) & 3)) & 3) << 4);
}

// ---------------- split fp32 -> bf16 hi/lo ----------------
__global__ __launch_bounds__(256) void split_kernel(
    const float* __restrict__ src, __nv_bfloat16* __restrict__ hi,
    __nv_bfloat16* __restrict__ lo, int n)
{
    int i = (blockIdx.x * 256 + threadIdx.x) * 4;
    if (i < n) {
        float4 x = *(const float4*)(src + i);
        __nv_bfloat16 h0 = __float2bfloat16(x.x);
        __nv_bfloat16 h1 = __float2bfloat16(x.y);
        __nv_bfloat16 h2 = __float2bfloat16(x.z);
        __nv_bfloat16 h3 = __float2bfloat16(x.w);
        __nv_bfloat162 H0 = {h0, h1}, H1 = {h2, h3};
        __nv_bfloat162 L0 = {__float2bfloat16(x.x - __bfloat162float(h0)),
                             __float2bfloat16(x.y - __bfloat162float(h1))};
        __nv_bfloat162 L1 = {__float2bfloat16(x.z - __bfloat162float(h2)),
                             __float2bfloat16(x.w - __bfloat162float(h3))};
        *(__nv_bfloat162*)(hi + i)     = H0;
        *(__nv_bfloat162*)(hi + i + 2) = H1;
        *(__nv_bfloat162*)(lo + i)     = L0;
        *(__nv_bfloat162*)(lo + i + 2) = L1;
    }
}

// ---------------- bf16x3 GEMM via mma.sync: Y[m,n] = sum_k X[m,k]*W[n,k] + b[n] ----
// 128x128 tile, BK=32, 256 threads (8 warps 2x4), warp tile 64x32,
// cp.async double buffer, XOR-swizzled smem, 3 mma passes (hh, hl, lh).
#define TILE_B 8192            // one 128x32 bf16 tile
#define STAGE_B (4 * TILE_B)   // Ahi, Alo, Bhi, Blo
#define GEMM_SMEM (2 * STAGE_B)

__global__ __launch_bounds__(256, 1) void gemm_bf16x3_mma(
    const __nv_bfloat16* __restrict__ Xhi, const __nv_bfloat16* __restrict__ Xlo,
    const __nv_bfloat16* __restrict__ Whi, const __nv_bfloat16* __restrict__ Wlo,
    const float* __restrict__ bias, float* __restrict__ Y, int N, int K)
{
    extern __shared__ char smraw[];
    const uint32_t sb = smem_u32(smraw);
    const int tid = threadIdx.x, lane = tid & 31, wid = tid >> 5;
    const int wm = wid & 1, wn = wid >> 1;
    const int m0 = blockIdx.y * 128, n0 = blockIdx.x * 128;

    float acc[4][4][4];
#pragma unroll
    for (int i = 0; i < 4; i++)
#pragma unroll
        for (int j = 0; j < 4; j++)
#pragma unroll
            for (int c = 0; c < 4; c++) acc[i][j][c] = 0.0f;

    const __nv_bfloat16* gsrc[4] = {Xhi, Xlo, Whi, Wlo};

    auto load_stage = [&](int buf, int k0) {
#pragma unroll
        for (int t = 0; t < 8; t++) {
            const int tile = t >> 1;                      // compile-time after unroll
            const int ci = ((t & 1) << 8) + tid;          // 0..511 chunk within tile
            const int row = ci >> 2;
            const int c = ci & 3;
            const int r0 = (tile < 2) ? m0 : n0;
            const __nv_bfloat16* g = gsrc[tile] + (size_t)(r0 + row) * K + k0 + c * 8;
            uint32_t sa = swz(sb + buf * STAGE_B + tile * TILE_B, row, c);
            cpasync16(sa, g);
        }
        asm volatile("cp.async.commit_group;" ::: "memory");
    };

    auto compute_stage = [&](int buf) {
        const uint32_t base = sb + buf * STAGE_B;
        const uint32_t Ahi_b = base, Alo_b = base + TILE_B;
        const uint32_t Bhi_b = base + 2 * TILE_B, Blo_b = base + 3 * TILE_B;
        const int a_row = wm * 64 + (lane & 15);
        const int a_kc = (lane >> 4) & 1;
        const int b_row = wn * 32 + (lane & 7) + ((lane >> 4) & 1) * 8;
        const int b_kc = (lane >> 3) & 1;
#pragma unroll
        for (int k2 = 0; k2 < 2; k2++) {
            const int kcb = k2 * 2;
            uint32_t ahi[4][4], alo[4][4], bhi[2][4], blo[2][4];
#pragma unroll
            for (int mi = 0; mi < 4; mi++) {
                ldsm4(ahi[mi], swz(Ahi_b, a_row + mi * 16, kcb + a_kc));
                ldsm4(alo[mi], swz(Alo_b, a_row + mi * 16, kcb + a_kc));
            }
#pragma unroll
            for (int nj = 0; nj < 2; nj++) {
                ldsm4(bhi[nj], swz(Bhi_b, b_row + nj * 16, kcb + b_kc));
                ldsm4(blo[nj], swz(Blo_b, b_row + nj * 16, kcb + b_kc));
            }
#pragma unroll
            for (int mi = 0; mi < 4; mi++)
#pragma unroll
                for (int ni = 0; ni < 4; ni++) {
                    const uint32_t* bh = &bhi[ni >> 1][(ni & 1) * 2];
                    const uint32_t* bl = &blo[ni >> 1][(ni & 1) * 2];
                    mma_bf16(acc[mi][ni], ahi[mi], bh);
                    mma_bf16(acc[mi][ni], ahi[mi], bl);
                    mma_bf16(acc[mi][ni], alo[mi], bh);
                }
        }
    };

    const int KS = K >> 5;
    load_stage(0, 0);
    load_stage(1, 32);

    for (int s = 0; s < KS; s++) {
        if (s + 2 < KS) {
            asm volatile("cp.async.wait_group 1;" ::: "memory");
        } else {
            asm volatile("cp.async.wait_group 0;" ::: "memory");
        }
        __syncthreads();
        compute_stage(s & 1);
        __syncthreads();
        if (s + 2 < KS) load_stage(s & 1, (s + 2) * 32);
    }

    // epilogue: bias + direct float2 stores from mma fragments
#pragma unroll
    for (int mi = 0; mi < 4; mi++) {
        const int r0 = m0 + wm * 64 + mi * 16 + (lane >> 2);
#pragma unroll
        for (int ni = 0; ni < 4; ni++) {
            const int col = n0 + wn * 32 + ni * 8 + (lane & 3) * 2;
            float2 bv = *(const float2*)(bias + col);
            float2 v0 = {acc[mi][ni][0] + bv.x, acc[mi][ni][1] + bv.y};
            float2 v1 = {acc[mi][ni][2] + bv.x, acc[mi][ni][3] + bv.y};
            *(float2*)(Y + (size_t)r0 * N + col) = v0;
            *(float2*)(Y + (size_t)(r0 + 8) * N + col) = v1;
        }
    }
}

// ---------------- Flash attention (fp32, causal + key padding mask) ----------------
__global__ __launch_bounds__(128) void flash_attn_kernel(
    const float* __restrict__ Q, const float* __restrict__ K,
    const float* __restrict__ V, const int* __restrict__ AM,
    float* __restrict__ O)
{
    __shared__ float Ks[32][64];
    __shared__ float Vs[32][64];
    __shared__ int   Ms[32];

    const int qb  = blockIdx.x;
    const int h   = blockIdx.y;
    const int b   = blockIdx.z;
    const int kvh = h >> 2;
    const int r   = qb * 128 + threadIdx.x;

    float qreg[64];
    const float* qp = Q + (((size_t)b * LQ + r) * NQH + h) * HDIM;
#pragma unroll
    for (int d = 0; d < 64; d += 4) {
        float4 t = *(const float4*)(qp + d);
        qreg[d + 0] = t.x * 0.125f;
        qreg[d + 1] = t.y * 0.125f;
        qreg[d + 2] = t.z * 0.125f;
        qreg[d + 3] = t.w * 0.125f;
    }

    float acc[64];
#pragma unroll
    for (int d = 0; d < 64; d++) acc[d] = 0.0f;
    float mrun = -1e30f, lrun = 0.0f;

    const int kend = qb * 128 + 128;
    for (int t0 = 0; t0 < kend; t0 += 32) {
        __syncthreads();
#pragma unroll
        for (int ii = 0; ii < 4; ii++) {
            int i = threadIdx.x + ii * 128;
            int row = i >> 4;
            int c   = (i & 15) << 2;
            const size_t base = (((size_t)b * LQ + t0 + row) * NKVH + kvh) * HDIM + c;
            *(float4*)&Ks[row][c] = *(const float4*)(K + base);
            *(float4*)&Vs[row][c] = *(const float4*)(V + base);
        }
        if (threadIdx.x < 32) Ms[threadIdx.x] = AM[(size_t)b * LQ + t0 + threadIdx.x];
        __syncthreads();

        float s[32];
#pragma unroll
        for (int j = 0; j < 32; j++) {
            float s0 = 0.f, s1 = 0.f, s2 = 0.f, s3 = 0.f;
#pragma unroll
            for (int d = 0; d < 64; d += 4) {
                float4 kk = *(const float4*)&Ks[j][d];
                s0 += qreg[d + 0] * kk.x;
                s1 += qreg[d + 1] * kk.y;
                s2 += qreg[d + 2] * kk.z;
                s3 += qreg[d + 3] * kk.w;
            }
            float sv = (s0 + s1) + (s2 + s3);
            int key = t0 + j;
            s[j] = (key <= r && Ms[j] != 0) ? sv : -1e30f;
        }

        float mt = mrun;
#pragma unroll
        for (int j = 0; j < 32; j++) mt = fmaxf(mt, s[j]);
        float scale = __expf(mrun - mt);
        float psum = 0.0f;
#pragma unroll
        for (int j = 0; j < 32; j++) {
            float p = __expf(s[j] - mt);
            s[j] = p;
            psum += p;
        }
        mrun = mt;
        lrun = lrun * scale + psum;

#pragma unroll
        for (int d = 0; d < 64; d++) acc[d] *= scale;
#pragma unroll
        for (int j = 0; j < 32; j++) {
            float p = s[j];
#pragma unroll
            for (int d = 0; d < 64; d += 4) {
                float4 vv = *(const float4*)&Vs[j][d];
                acc[d + 0] += p * vv.x;
                acc[d + 1] += p * vv.y;
                acc[d + 2] += p * vv.z;
                acc[d + 3] += p * vv.w;
            }
        }
    }

    float inv = 1.0f / lrun;
    float* op = O + (((size_t)b * LQ + r) * NQH + h) * HDIM;
#pragma unroll
    for (int d = 0; d < 64; d += 4) {
        float4 o4;
        o4.x = acc[d + 0] * inv;
        o4.y = acc[d + 1] * inv;
        o4.z = acc[d + 2] * inv;
        o4.w = acc[d + 3] * inv;
        *(float4*)(op + d) = o4;
    }
}

// ---------------- launch ----------------
extern "C" void kernel_launch(void* const* d_in, const int* in_sizes, int n_in,
                              void* d_out, int out_size)
{
    const float* x   = (const float*)d_in[0];
    const int*   am  = (const int*)  d_in[1];
    const float* q_w = (const float*)d_in[2];
    const float* q_b = (const float*)d_in[3];
    const float* k_w = (const float*)d_in[4];
    const float* k_b = (const float*)d_in[5];
    const float* v_w = (const float*)d_in[6];
    const float* v_b = (const float*)d_in[7];
    const float* o_w = (const float*)d_in[8];
    const float* o_b = (const float*)d_in[9];
    float* out = (float*)d_out;

    float *gq, *gk, *gv, *ga;
    cudaGetSymbolAddress((void**)&gq, g_q);
    cudaGetSymbolAddress((void**)&gk, g_k);
    cudaGetSymbolAddress((void**)&gv, g_v);
    cudaGetSymbolAddress((void**)&ga, g_attn);
    __nv_bfloat16 *xhi, *xlo, *qwh, *qwl, *kwh, *kwl, *vwh, *vwl, *owh, *owl, *ahi, *alo;
    cudaGetSymbolAddress((void**)&xhi, g_xhi);  cudaGetSymbolAddress((void**)&xlo, g_xlo);
    cudaGetSymbolAddress((void**)&qwh, g_qwhi); cudaGetSymbolAddress((void**)&qwl, g_qwlo);
    cudaGetSymbolAddress((void**)&kwh, g_kwhi); cudaGetSymbolAddress((void**)&kwl, g_kwlo);
    cudaGetSymbolAddress((void**)&vwh, g_vwhi); cudaGetSymbolAddress((void**)&vwl, g_vwlo);
    cudaGetSymbolAddress((void**)&owh, g_owhi); cudaGetSymbolAddress((void**)&owl, g_owlo);
    cudaGetSymbolAddress((void**)&ahi, g_ahi);  cudaGetSymbolAddress((void**)&alo, g_alo);

    static bool attr_done = false;
    if (!attr_done) {
        cudaFuncSetAttribute(gemm_bf16x3_mma, cudaFuncAttributeMaxDynamicSharedMemorySize, GEMM_SMEM);
        attr_done = true;
    }

    auto split = [](const float* s, __nv_bfloat16* h, __nv_bfloat16* l, int n) {
        split_kernel<<<(n / 4 + 255) / 256, 256>>>(s, h, l, n);
    };
    split(x, xhi, xlo, MROWS * HIDDEN);
    split(q_w, qwh, qwl, HIDDEN * HIDDEN);
    split(k_w, kwh, kwl, KVDIM * HIDDEN);
    split(v_w, vwh, vwl, KVDIM * HIDDEN);
    split(o_w, owh, owl, HIDDEN * HIDDEN);

    gemm_bf16x3_mma<<<dim3(HIDDEN / 128, MROWS / 128), 256, GEMM_SMEM>>>(
        xhi, xlo, qwh, qwl, q_b, gq, HIDDEN, HIDDEN);
    gemm_bf16x3_mma<<<dim3(KVDIM / 128, MROWS / 128), 256, GEMM_SMEM>>>(
        xhi, xlo, kwh, kwl, k_b, gk, KVDIM, HIDDEN);
    gemm_bf16x3_mma<<<dim3(KVDIM / 128, MROWS / 128), 256, GEMM_SMEM>>>(
        xhi, xlo, vwh, vwl, v_b, gv, KVDIM, HIDDEN);

    flash_attn_kernel<<<dim3(LQ / 128, NQH, BATCH), 128>>>(gq, gk, gv, am, ga);

    split(ga, ahi, alo, MROWS * HIDDEN);
    gemm_bf16x3_mma<<<dim3(HIDDEN / 128, MROWS / 128), 256, GEMM_SMEM>>>(
        ahi, alo, owh, owl, o_b, out, HIDDEN, HIDDEN);
}

// round 4
// speedup vs baseline: 3.9045x; 2.2824x over previous
#include <cuda_runtime.h>
#include <cuda_bf16.h>
#include <cstdint>

#define HIDDEN 2048
#define LQ 2048
#define BATCH 2
#define NQH 32
#define NKVH 8
#define HDIM 64
#define MROWS (BATCH * LQ)   // 4096
#define KVDIM (NKVH * HDIM)  // 512

// Q pre-scale: 1/sqrt(64) * log2(e)  (softmax done in exp2 domain)
#define QSCALE (0.125f * 1.4426950408889634f)

// ---------------- scratch (device globals) ----------------
__device__ __align__(16) __nv_bfloat16 g_xhi[MROWS * HIDDEN];
__device__ __align__(16) __nv_bfloat16 g_xlo[MROWS * HIDDEN];
__device__ __align__(16) __nv_bfloat16 g_qwhi[HIDDEN * HIDDEN];
__device__ __align__(16) __nv_bfloat16 g_qwlo[HIDDEN * HIDDEN];
__device__ __align__(16) __nv_bfloat16 g_kwhi[KVDIM * HIDDEN];
__device__ __align__(16) __nv_bfloat16 g_kwlo[KVDIM * HIDDEN];
__device__ __align__(16) __nv_bfloat16 g_vwhi[KVDIM * HIDDEN];
__device__ __align__(16) __nv_bfloat16 g_vwlo[KVDIM * HIDDEN];
__device__ __align__(16) __nv_bfloat16 g_owhi[HIDDEN * HIDDEN];
__device__ __align__(16) __nv_bfloat16 g_owlo[HIDDEN * HIDDEN];
// projected Q/K/V planes (bf16 hi/lo)
__device__ __align__(16) __nv_bfloat16 g_qhi[MROWS * HIDDEN];
__device__ __align__(16) __nv_bfloat16 g_qlo[MROWS * HIDDEN];
__device__ __align__(16) __nv_bfloat16 g_khi[MROWS * KVDIM];
__device__ __align__(16) __nv_bfloat16 g_klo[MROWS * KVDIM];
__device__ __align__(16) __nv_bfloat16 g_vhi[MROWS * KVDIM];
__device__ __align__(16) __nv_bfloat16 g_vlo[MROWS * KVDIM];
// attention output planes
__device__ __align__(16) __nv_bfloat16 g_ahi[MROWS * HIDDEN];
__device__ __align__(16) __nv_bfloat16 g_alo[MROWS * HIDDEN];

// ---------------- PTX helpers (sm_80-era base ISA) ----------------
__device__ __forceinline__ uint32_t smem_u32(const void* p) {
    uint32_t a;
    asm("{ .reg .u64 t; cvta.to.shared.u64 t, %1; cvt.u32.u64 %0, t; }" : "=r"(a) : "l"(p));
    return a;
}
__device__ __forceinline__ void cpasync16(uint32_t saddr, const void* g) {
    asm volatile("cp.async.cg.shared.global [%0], [%1], 16;" :: "r"(saddr), "l"(g) : "memory");
}
__device__ __forceinline__ void ldsm4(uint32_t* r, uint32_t addr) {
    asm volatile("ldmatrix.sync.aligned.m8n8.x4.shared.b16 {%0,%1,%2,%3}, [%4];"
        : "=r"(r[0]), "=r"(r[1]), "=r"(r[2]), "=r"(r[3]) : "r"(addr));
}
__device__ __forceinline__ void ldsm4t(uint32_t* r, uint32_t addr) {
    asm volatile("ldmatrix.sync.aligned.m8n8.x4.trans.shared.b16 {%0,%1,%2,%3}, [%4];"
        : "=r"(r[0]), "=r"(r[1]), "=r"(r[2]), "=r"(r[3]) : "r"(addr));
}
__device__ __forceinline__ void mma_bf16(float* c, const uint32_t* a, const uint32_t* b) {
    asm volatile("mma.sync.aligned.m16n8k16.row.col.f32.bf16.bf16.f32 "
        "{%0,%1,%2,%3}, {%4,%5,%6,%7}, {%8,%9}, {%0,%1,%2,%3};"
        : "+f"(c[0]), "+f"(c[1]), "+f"(c[2]), "+f"(c[3])
        : "r"(a[0]), "r"(a[1]), "r"(a[2]), "r"(a[3]), "r"(b[0]), "r"(b[1]));
}
__device__ __forceinline__ uint32_t pack_bf16(float x, float y) {
    __nv_bfloat162 t = {__float2bfloat16(x), __float2bfloat16(y)};
    return *reinterpret_cast<uint32_t*>(&t);
}
// swizzled smem addr for GEMM (64B rows, BK=32 bf16)
__device__ __forceinline__ uint32_t swz(uint32_t tb, int row, int kc) {
    return tb + row * 64 + (((kc ^ ((row >> 1) & 3)) & 3) << 4);
}

// ---------------- split fp32 -> bf16 hi/lo ----------------
__global__ __launch_bounds__(256) void split_kernel(
    const float* __restrict__ src, __nv_bfloat16* __restrict__ hi,
    __nv_bfloat16* __restrict__ lo, int n)
{
    int i = (blockIdx.x * 256 + threadIdx.x) * 4;
    if (i < n) {
        float4 x = *(const float4*)(src + i);
        __nv_bfloat16 h0 = __float2bfloat16(x.x);
        __nv_bfloat16 h1 = __float2bfloat16(x.y);
        __nv_bfloat16 h2 = __float2bfloat16(x.z);
        __nv_bfloat16 h3 = __float2bfloat16(x.w);
        __nv_bfloat162 H0 = {h0, h1}, H1 = {h2, h3};
        __nv_bfloat162 L0 = {__float2bfloat16(x.x - __bfloat162float(h0)),
                             __float2bfloat16(x.y - __bfloat162float(h1))};
        __nv_bfloat162 L1 = {__float2bfloat16(x.z - __bfloat162float(h2)),
                             __float2bfloat16(x.w - __bfloat162float(h3))};
        *(__nv_bfloat162*)(hi + i)     = H0;
        *(__nv_bfloat162*)(hi + i + 2) = H1;
        *(__nv_bfloat162*)(lo + i)     = L0;
        *(__nv_bfloat162*)(lo + i + 2) = L1;
    }
}

// ---------------- bf16x3 GEMM: Y = X*W^T + b ----------------
// MODE 0: write fp32 Y.  MODE 1: write (acc+bias)*oscale split into hi/lo bf16.
#define TILE_B 8192
#define STAGE_B (4 * TILE_B)
#define GEMM_SMEM (2 * STAGE_B)

template <int MODE>
__global__ __launch_bounds__(256, 1) void gemm_bf16x3_mma(
    const __nv_bfloat16* __restrict__ Xhi, const __nv_bfloat16* __restrict__ Xlo,
    const __nv_bfloat16* __restrict__ Whi, const __nv_bfloat16* __restrict__ Wlo,
    const float* __restrict__ bias, float* __restrict__ Y,
    __nv_bfloat16* __restrict__ Yhi, __nv_bfloat16* __restrict__ Ylo,
    float oscale, int N, int K)
{
    extern __shared__ char smraw[];
    const uint32_t sb = smem_u32(smraw);
    const int tid = threadIdx.x, lane = tid & 31, wid = tid >> 5;
    const int wm = wid & 1, wn = wid >> 1;
    const int m0 = blockIdx.y * 128, n0 = blockIdx.x * 128;

    float acc[4][4][4];
#pragma unroll
    for (int i = 0; i < 4; i++)
#pragma unroll
        for (int j = 0; j < 4; j++)
#pragma unroll
            for (int c = 0; c < 4; c++) acc[i][j][c] = 0.0f;

    const __nv_bfloat16* gsrc[4] = {Xhi, Xlo, Whi, Wlo};

    auto load_stage = [&](int buf, int k0) {
#pragma unroll
        for (int t = 0; t < 8; t++) {
            const int tile = t >> 1;
            const int ci = ((t & 1) << 8) + tid;
            const int row = ci >> 2;
            const int c = ci & 3;
            const int r0 = (tile < 2) ? m0 : n0;
            const __nv_bfloat16* g = gsrc[tile] + (size_t)(r0 + row) * K + k0 + c * 8;
            cpasync16(swz(sb + buf * STAGE_B + tile * TILE_B, row, c), g);
        }
        asm volatile("cp.async.commit_group;" ::: "memory");
    };

    auto compute_stage = [&](int buf) {
        const uint32_t base = sb + buf * STAGE_B;
        const uint32_t Ahi_b = base, Alo_b = base + TILE_B;
        const uint32_t Bhi_b = base + 2 * TILE_B, Blo_b = base + 3 * TILE_B;
        const int a_row = wm * 64 + (lane & 15);
        const int a_kc = (lane >> 4) & 1;
        const int b_row = wn * 32 + (lane & 7) + ((lane >> 4) & 1) * 8;
        const int b_kc = (lane >> 3) & 1;
#pragma unroll
        for (int k2 = 0; k2 < 2; k2++) {
            const int kcb = k2 * 2;
            uint32_t ahi[4][4], alo[4][4], bhi[2][4], blo[2][4];
#pragma unroll
            for (int mi = 0; mi < 4; mi++) {
                ldsm4(ahi[mi], swz(Ahi_b, a_row + mi * 16, kcb + a_kc));
                ldsm4(alo[mi], swz(Alo_b, a_row + mi * 16, kcb + a_kc));
            }
#pragma unroll
            for (int nj = 0; nj < 2; nj++) {
                ldsm4(bhi[nj], swz(Bhi_b, b_row + nj * 16, kcb + b_kc));
                ldsm4(blo[nj], swz(Blo_b, b_row + nj * 16, kcb + b_kc));
            }
#pragma unroll
            for (int mi = 0; mi < 4; mi++)
#pragma unroll
                for (int ni = 0; ni < 4; ni++) {
                    const uint32_t* bh = &bhi[ni >> 1][(ni & 1) * 2];
                    const uint32_t* bl = &blo[ni >> 1][(ni & 1) * 2];
                    mma_bf16(acc[mi][ni], ahi[mi], bh);
                    mma_bf16(acc[mi][ni], ahi[mi], bl);
                    mma_bf16(acc[mi][ni], alo[mi], bh);
                }
        }
    };

    const int KS = K >> 5;
    load_stage(0, 0);
    load_stage(1, 32);

    for (int s = 0; s < KS; s++) {
        if (s + 2 < KS) {
            asm volatile("cp.async.wait_group 1;" ::: "memory");
        } else {
            asm volatile("cp.async.wait_group 0;" ::: "memory");
        }
        __syncthreads();
        compute_stage(s & 1);
        __syncthreads();
        if (s + 2 < KS) load_stage(s & 1, (s + 2) * 32);
    }

#pragma unroll
    for (int mi = 0; mi < 4; mi++) {
        const int r0 = m0 + wm * 64 + mi * 16 + (lane >> 2);
#pragma unroll
        for (int ni = 0; ni < 4; ni++) {
            const int col = n0 + wn * 32 + ni * 8 + (lane & 3) * 2;
            float2 bv = *(const float2*)(bias + col);
            if (MODE == 0) {
                float2 v0 = {acc[mi][ni][0] + bv.x, acc[mi][ni][1] + bv.y};
                float2 v1 = {acc[mi][ni][2] + bv.x, acc[mi][ni][3] + bv.y};
                *(float2*)(Y + (size_t)r0 * N + col) = v0;
                *(float2*)(Y + (size_t)(r0 + 8) * N + col) = v1;
            } else {
                float v0 = (acc[mi][ni][0] + bv.x) * oscale;
                float v1 = (acc[mi][ni][1] + bv.y) * oscale;
                float v2 = (acc[mi][ni][2] + bv.x) * oscale;
                float v3 = (acc[mi][ni][3] + bv.y) * oscale;
                float h0 = __bfloat162float(__float2bfloat16(v0));
                float h1 = __bfloat162float(__float2bfloat16(v1));
                float h2 = __bfloat162float(__float2bfloat16(v2));
                float h3 = __bfloat162float(__float2bfloat16(v3));
                *(uint32_t*)(Yhi + (size_t)r0 * N + col)       = pack_bf16(v0, v1);
                *(uint32_t*)(Ylo + (size_t)r0 * N + col)       = pack_bf16(v0 - h0, v1 - h1);
                *(uint32_t*)(Yhi + (size_t)(r0 + 8) * N + col) = pack_bf16(v2, v3);
                *(uint32_t*)(Ylo + (size_t)(r0 + 8) * N + col) = pack_bf16(v2 - h2, v3 - h3);
            }
        }
    }
}

// ---------------- tensor-core flash attention (bf16x3, causal + pad mask) --------
// grid (L/128, NQH, B); 256 threads (8 warps); warp w owns q rows qb*128+w*16..+15.
// KV tiles of 64 keys, double buffered. smem rows padded to 144B.
#define KV_PLANE 9216          // 64 rows * 144B
#define KV_BUF   (4 * KV_PLANE)
#define MS_OFF   (2 * KV_BUF)  // 73728
#define FLASH_SMEM (MS_OFF + 512)

__global__ __launch_bounds__(256, 1) void flash_tc(
    const __nv_bfloat16* __restrict__ Qhi, const __nv_bfloat16* __restrict__ Qlo,
    const __nv_bfloat16* __restrict__ Khi, const __nv_bfloat16* __restrict__ Klo,
    const __nv_bfloat16* __restrict__ Vhi, const __nv_bfloat16* __restrict__ Vlo,
    const int* __restrict__ AM,
    __nv_bfloat16* __restrict__ Ohi, __nv_bfloat16* __restrict__ Olo)
{
    extern __shared__ char smraw[];
    const uint32_t sb = smem_u32(smraw);
    const int tid = threadIdx.x, lane = tid & 31, w = tid >> 5;
    const int qb = blockIdx.x, h = blockIdx.y, b = blockIdx.z;
    const int kvh = h >> 2;
    const int rbase = qb * 128 + w * 16;
    const int g = lane >> 2;              // row within 8
    const int qd = lane & 3;              // quad col idx

    // ---- stage Q (hi @ 0, lo @ 18432) ----
#pragma unroll
    for (int j = 0; j < 8; j++) {
        int c = tid + j * 256;            // 0..2047
        int pl = c >> 10, row = (c >> 3) & 127, ch = c & 7;
        const __nv_bfloat16* src = (pl ? Qlo : Qhi)
            + ((size_t)(b * LQ + qb * 128 + row) * NQH + h) * HDIM + ch * 8;
        cpasync16(sb + pl * 18432 + row * 144 + ch * 16, src);
    }
    asm volatile("cp.async.commit_group;" ::: "memory");
    asm volatile("cp.async.wait_group 0;" ::: "memory");
    __syncthreads();

    uint32_t qh[4][4], ql[4][4];
#pragma unroll
    for (int kt = 0; kt < 4; kt++) {
        uint32_t off = (uint32_t)((w * 16 + (lane & 15)) * 144 + kt * 32 + ((lane >> 4) & 1) * 16);
        ldsm4(qh[kt], sb + off);
        ldsm4(ql[kt], sb + 18432 + off);
    }
    __syncthreads();   // all warps done reading Q smem before KV overwrites buf0

    const __nv_bfloat16* kvsrc[4] = {Khi, Klo, Vhi, Vlo};
    auto load_kv = [&](int buf, int t0) {
#pragma unroll
        for (int j = 0; j < 8; j++) {
            int c = tid + j * 256;        // 0..2047
            int pl = c >> 9, row = (c >> 3) & 63, ch = c & 7;
            const __nv_bfloat16* src = kvsrc[pl]
                + ((size_t)(b * LQ + t0 + row) * NKVH + kvh) * HDIM + ch * 8;
            cpasync16(sb + buf * KV_BUF + pl * KV_PLANE + row * 144 + ch * 16, src);
        }
        if (tid < 16)
            cpasync16(sb + MS_OFF + buf * 256 + tid * 16, AM + (size_t)b * LQ + t0 + tid * 4);
        asm volatile("cp.async.commit_group;" ::: "memory");
    };

    const int NI = 2 * qb + 2;
    load_kv(0, 0);
    if (NI > 1) load_kv(1, 64);

    float m0 = -1e30f, m1 = -1e30f, l0 = 0.0f, l1 = 0.0f;
    float o[8][4];
#pragma unroll
    for (int i = 0; i < 8; i++)
#pragma unroll
        for (int c = 0; c < 4; c++) o[i][c] = 0.0f;

    for (int it = 0; it < NI; it++) {
        if (it + 1 < NI) {
            asm volatile("cp.async.wait_group 1;" ::: "memory");
        } else {
            asm volatile("cp.async.wait_group 0;" ::: "memory");
        }
        __syncthreads();
        const int buf = it & 1;
        const int t0 = it * 64;
        const uint32_t kvb = sb + buf * KV_BUF;
        const int* Ms = (const int*)(smraw + MS_OFF + buf * 256);

        // ---- S = Q K^T (3-pass) ----
        float sc[8][4];
#pragma unroll
        for (int i = 0; i < 8; i++)
#pragma unroll
            for (int c = 0; c < 4; c++) sc[i][c] = 0.0f;

#pragma unroll
        for (int kt = 0; kt < 4; kt++) {
            uint32_t bh[4][4], bl[4][4];
#pragma unroll
            for (int ng = 0; ng < 4; ng++) {
                uint32_t off = (uint32_t)((ng * 16 + (lane & 15)) * 144 + kt * 32 + ((lane >> 4) & 1) * 16);
                ldsm4(bh[ng], kvb + off);                // Khi
                ldsm4(bl[ng], kvb + KV_PLANE + off);     // Klo
            }
#pragma unroll
            for (int ng = 0; ng < 4; ng++)
#pragma unroll
                for (int hh = 0; hh < 2; hh++) {
                    uint32_t fh[2] = {bh[ng][hh], bh[ng][hh + 2]};
                    uint32_t fl[2] = {bl[ng][hh], bl[ng][hh + 2]};
                    mma_bf16(sc[2 * ng + hh], qh[kt], fh);
                    mma_bf16(sc[2 * ng + hh], qh[kt], fl);
                    mma_bf16(sc[2 * ng + hh], ql[kt], fh);
                }
        }

        // ---- mask (pad + causal) ----
        const int rowA = rbase + g, rowB = rowA + 8;
        const bool needc = (t0 + 63 > rbase);
#pragma unroll
        for (int ni = 0; ni < 8; ni++) {
            int c0 = ni * 8 + qd * 2, c1 = c0 + 1;
            bool v0 = (Ms[c0] != 0), v1 = (Ms[c1] != 0);
            int g0 = t0 + c0, g1 = t0 + c1;
            if (!v0 || (needc && g0 > rowA)) sc[ni][0] = -1e30f;
            if (!v1 || (needc && g1 > rowA)) sc[ni][1] = -1e30f;
            if (!v0 || (needc && g0 > rowB)) sc[ni][2] = -1e30f;
            if (!v1 || (needc && g1 > rowB)) sc[ni][3] = -1e30f;
        }

        // ---- online softmax (exp2 domain) ----
        float mn0 = m0, mn1 = m1;
#pragma unroll
        for (int ni = 0; ni < 8; ni++) {
            mn0 = fmaxf(mn0, fmaxf(sc[ni][0], sc[ni][1]));
            mn1 = fmaxf(mn1, fmaxf(sc[ni][2], sc[ni][3]));
        }
        mn0 = fmaxf(mn0, __shfl_xor_sync(0xffffffffu, mn0, 1));
        mn0 = fmaxf(mn0, __shfl_xor_sync(0xffffffffu, mn0, 2));
        mn1 = fmaxf(mn1, __shfl_xor_sync(0xffffffffu, mn1, 1));
        mn1 = fmaxf(mn1, __shfl_xor_sync(0xffffffffu, mn1, 2));
        float s0 = exp2f(m0 - mn0), s1 = exp2f(m1 - mn1);
        float rs0 = 0.0f, rs1 = 0.0f;
#pragma unroll
        for (int ni = 0; ni < 8; ni++) {
            sc[ni][0] = exp2f(sc[ni][0] - mn0);
            sc[ni][1] = exp2f(sc[ni][1] - mn0);
            sc[ni][2] = exp2f(sc[ni][2] - mn1);
            sc[ni][3] = exp2f(sc[ni][3] - mn1);
            rs0 += sc[ni][0] + sc[ni][1];
            rs1 += sc[ni][2] + sc[ni][3];
        }
        rs0 += __shfl_xor_sync(0xffffffffu, rs0, 1);
        rs0 += __shfl_xor_sync(0xffffffffu, rs0, 2);
        rs1 += __shfl_xor_sync(0xffffffffu, rs1, 1);
        rs1 += __shfl_xor_sync(0xffffffffu, rs1, 2);
        l0 = l0 * s0 + rs0;
        l1 = l1 * s1 + rs1;
        m0 = mn0; m1 = mn1;
#pragma unroll
        for (int ni = 0; ni < 8; ni++) {
            o[ni][0] *= s0; o[ni][1] *= s0;
            o[ni][2] *= s1; o[ni][3] *= s1;
        }

        // ---- P hi/lo fragments ----
        uint32_t ph[4][4], pl[4][4];
#pragma unroll
        for (int kt = 0; kt < 4; kt++)
#pragma unroll
            for (int j = 0; j < 4; j++) {
                int ni = 2 * kt + (j >> 1);
                int e = (j & 1) * 2;
                float x0 = sc[ni][e], x1 = sc[ni][e + 1];
                float h0 = __bfloat162float(__float2bfloat16(x0));
                float h1 = __bfloat162float(__float2bfloat16(x1));
                ph[kt][j] = pack_bf16(x0, x1);
                pl[kt][j] = pack_bf16(x0 - h0, x1 - h1);
            }

        // ---- O += P V (3-pass) ----
#pragma unroll
        for (int kt = 0; kt < 4; kt++)
#pragma unroll
            for (int dg = 0; dg < 4; dg++) {
                uint32_t vh[4], vl[4];
                uint32_t off = (uint32_t)((kt * 16 + (lane & 15)) * 144 + dg * 32 + ((lane >> 4) & 1) * 16);
                ldsm4t(vh, kvb + 2 * KV_PLANE + off);     // Vhi
                ldsm4t(vl, kvb + 3 * KV_PLANE + off);     // Vlo
                mma_bf16(o[2 * dg],     ph[kt], &vh[0]);
                mma_bf16(o[2 * dg],     ph[kt], &vl[0]);
                mma_bf16(o[2 * dg],     pl[kt], &vh[0]);
                mma_bf16(o[2 * dg + 1], ph[kt], &vh[2]);
                mma_bf16(o[2 * dg + 1], ph[kt], &vl[2]);
                mma_bf16(o[2 * dg + 1], pl[kt], &vh[2]);
            }

        __syncthreads();
        if (it + 2 < NI) load_kv(buf, (it + 2) * 64);
    }

    // ---- epilogue: normalize, split hi/lo, store ----
    const float inv0 = 1.0f / l0, inv1 = 1.0f / l1;
    const int rowA = rbase + g;
#pragma unroll
    for (int ni = 0; ni < 8; ni++) {
        int col = ni * 8 + qd * 2;
        float a0 = o[ni][0] * inv0, a1 = o[ni][1] * inv0;
        float b0 = o[ni][2] * inv1, b1 = o[ni][3] * inv1;
        float h0 = __bfloat162float(__float2bfloat16(a0));
        float h1 = __bfloat162float(__float2bfloat16(a1));
        float h2 = __bfloat162float(__float2bfloat16(b0));
        float h3 = __bfloat162float(__float2bfloat16(b1));
        size_t baseA = ((size_t)(b * LQ + rowA) * NQH + h) * HDIM + col;
        size_t baseB = ((size_t)(b * LQ + rowA + 8) * NQH + h) * HDIM + col;
        *(uint32_t*)(Ohi + baseA) = pack_bf16(a0, a1);
        *(uint32_t*)(Olo + baseA) = pack_bf16(a0 - h0, a1 - h1);
        *(uint32_t*)(Ohi + baseB) = pack_bf16(b0, b1);
        *(uint32_t*)(Olo + baseB) = pack_bf16(b0 - h2, b1 - h3);
    }
}

// ---------------- launch ----------------
extern "C" void kernel_launch(void* const* d_in, const int* in_sizes, int n_in,
                              void* d_out, int out_size)
{
    const float* x   = (const float*)d_in[0];
    const int*   am  = (const int*)  d_in[1];
    const float* q_w = (const float*)d_in[2];
    const float* q_b = (const float*)d_in[3];
    const float* k_w = (const float*)d_in[4];
    const float* k_b = (const float*)d_in[5];
    const float* v_w = (const float*)d_in[6];
    const float* v_b = (const float*)d_in[7];
    const float* o_w = (const float*)d_in[8];
    const float* o_b = (const float*)d_in[9];
    float* out = (float*)d_out;

    __nv_bfloat16 *xhi, *xlo, *qwh, *qwl, *kwh, *kwl, *vwh, *vwl, *owh, *owl;
    __nv_bfloat16 *qhi, *qlo, *khi, *klo, *vhi, *vlo, *ahi, *alo;
    cudaGetSymbolAddress((void**)&xhi, g_xhi);  cudaGetSymbolAddress((void**)&xlo, g_xlo);
    cudaGetSymbolAddress((void**)&qwh, g_qwhi); cudaGetSymbolAddress((void**)&qwl, g_qwlo);
    cudaGetSymbolAddress((void**)&kwh, g_kwhi); cudaGetSymbolAddress((void**)&kwl, g_kwlo);
    cudaGetSymbolAddress((void**)&vwh, g_vwhi); cudaGetSymbolAddress((void**)&vwl, g_vwlo);
    cudaGetSymbolAddress((void**)&owh, g_owhi); cudaGetSymbolAddress((void**)&owl, g_owlo);
    cudaGetSymbolAddress((void**)&qhi, g_qhi);  cudaGetSymbolAddress((void**)&qlo, g_qlo);
    cudaGetSymbolAddress((void**)&khi, g_khi);  cudaGetSymbolAddress((void**)&klo, g_klo);
    cudaGetSymbolAddress((void**)&vhi, g_vhi);  cudaGetSymbolAddress((void**)&vlo, g_vlo);
    cudaGetSymbolAddress((void**)&ahi, g_ahi);  cudaGetSymbolAddress((void**)&alo, g_alo);

    static bool attr_done = false;
    if (!attr_done) {
        cudaFuncSetAttribute(gemm_bf16x3_mma<0>, cudaFuncAttributeMaxDynamicSharedMemorySize, GEMM_SMEM);
        cudaFuncSetAttribute(gemm_bf16x3_mma<1>, cudaFuncAttributeMaxDynamicSharedMemorySize, GEMM_SMEM);
        cudaFuncSetAttribute(flash_tc, cudaFuncAttributeMaxDynamicSharedMemorySize, FLASH_SMEM);
        attr_done = true;
    }

    auto split = [](const float* s, __nv_bfloat16* h, __nv_bfloat16* l, int n) {
        split_kernel<<<(n / 4 + 255) / 256, 256>>>(s, h, l, n);
    };
    split(x, xhi, xlo, MROWS * HIDDEN);
    split(q_w, qwh, qwl, HIDDEN * HIDDEN);
    split(k_w, kwh, kwl, KVDIM * HIDDEN);
    split(v_w, vwh, vwl, KVDIM * HIDDEN);
    split(o_w, owh, owl, HIDDEN * HIDDEN);

    // projections -> bf16 hi/lo planes (Q gets softmax scale folded in)
    gemm_bf16x3_mma<1><<<dim3(HIDDEN / 128, MROWS / 128), 256, GEMM_SMEM>>>(
        xhi, xlo, qwh, qwl, q_b, nullptr, qhi, qlo, QSCALE, HIDDEN, HIDDEN);
    gemm_bf16x3_mma<1><<<dim3(KVDIM / 128, MROWS / 128), 256, GEMM_SMEM>>>(
        xhi, xlo, kwh, kwl, k_b, nullptr, khi, klo, 1.0f, KVDIM, HIDDEN);
    gemm_bf16x3_mma<1><<<dim3(KVDIM / 128, MROWS / 128), 256, GEMM_SMEM>>>(
        xhi, xlo, vwh, vwl, v_b, nullptr, vhi, vlo, 1.0f, KVDIM, HIDDEN);

    // tensor-core flash attention -> hi/lo planes
    flash_tc<<<dim3(LQ / 128, NQH, BATCH), 256, FLASH_SMEM>>>(
        qhi, qlo, khi, klo, vhi, vlo, am, ahi, alo);

    // output projection -> fp32
    gemm_bf16x3_mma<0><<<dim3(HIDDEN / 128, MROWS / 128), 256, GEMM_SMEM>>>(
        ahi, alo, owh, owl, o_b, out, nullptr, nullptr, 1.0f, HIDDEN, HIDDEN);
}

// round 5
// speedup vs baseline: 3.9359x; 1.0080x over previous
#include <cuda_runtime.h>
#include <cuda_bf16.h>
#include <cstdint>

#define HIDDEN 2048
#define LQ 2048
#define BATCH 2
#define NQH 32
#define NKVH 8
#define HDIM 64
#define MROWS (BATCH * LQ)   // 4096
#define KVDIM (NKVH * HDIM)  // 512

// Q pre-scale: 1/sqrt(64) * log2(e)  (softmax done in exp2 domain)
#define QSCALE (0.125f * 1.4426950408889634f)

// ---------------- scratch (device globals) ----------------
__device__ __align__(16) __nv_bfloat16 g_xhi[MROWS * HIDDEN];
__device__ __align__(16) __nv_bfloat16 g_xlo[MROWS * HIDDEN];
__device__ __align__(16) __nv_bfloat16 g_qwhi[HIDDEN * HIDDEN];
__device__ __align__(16) __nv_bfloat16 g_qwlo[HIDDEN * HIDDEN];
__device__ __align__(16) __nv_bfloat16 g_kwhi[KVDIM * HIDDEN];
__device__ __align__(16) __nv_bfloat16 g_kwlo[KVDIM * HIDDEN];
__device__ __align__(16) __nv_bfloat16 g_vwhi[KVDIM * HIDDEN];
__device__ __align__(16) __nv_bfloat16 g_vwlo[KVDIM * HIDDEN];
__device__ __align__(16) __nv_bfloat16 g_owhi[HIDDEN * HIDDEN];
__device__ __align__(16) __nv_bfloat16 g_owlo[HIDDEN * HIDDEN];
__device__ __align__(16) __nv_bfloat16 g_qhi[MROWS * HIDDEN];
__device__ __align__(16) __nv_bfloat16 g_qlo[MROWS * HIDDEN];
__device__ __align__(16) __nv_bfloat16 g_khi[MROWS * KVDIM];
__device__ __align__(16) __nv_bfloat16 g_klo[MROWS * KVDIM];
__device__ __align__(16) __nv_bfloat16 g_vhi[MROWS * KVDIM];
__device__ __align__(16) __nv_bfloat16 g_vlo[MROWS * KVDIM];
__device__ __align__(16) __nv_bfloat16 g_ahi[MROWS * HIDDEN];
__device__ __align__(16) __nv_bfloat16 g_alo[MROWS * HIDDEN];

// ---------------- PTX helpers (sm_80-era base ISA) ----------------
__device__ __forceinline__ uint32_t smem_u32(const void* p) {
    uint32_t a;
    asm("{ .reg .u64 t; cvta.to.shared.u64 t, %1; cvt.u32.u64 %0, t; }" : "=r"(a) : "l"(p));
    return a;
}
__device__ __forceinline__ void cpasync16(uint32_t saddr, const void* g) {
    asm volatile("cp.async.cg.shared.global [%0], [%1], 16;" :: "r"(saddr), "l"(g) : "memory");
}
__device__ __forceinline__ void ldsm4(uint32_t* r, uint32_t addr) {
    asm volatile("ldmatrix.sync.aligned.m8n8.x4.shared.b16 {%0,%1,%2,%3}, [%4];"
        : "=r"(r[0]), "=r"(r[1]), "=r"(r[2]), "=r"(r[3]) : "r"(addr));
}
__device__ __forceinline__ void ldsm4t(uint32_t* r, uint32_t addr) {
    asm volatile("ldmatrix.sync.aligned.m8n8.x4.trans.shared.b16 {%0,%1,%2,%3}, [%4];"
        : "=r"(r[0]), "=r"(r[1]), "=r"(r[2]), "=r"(r[3]) : "r"(addr));
}
__device__ __forceinline__ void mma_bf16(float* c, const uint32_t* a, const uint32_t* b) {
    asm volatile("mma.sync.aligned.m16n8k16.row.col.f32.bf16.bf16.f32 "
        "{%0,%1,%2,%3}, {%4,%5,%6,%7}, {%8,%9}, {%0,%1,%2,%3};"
        : "+f"(c[0]), "+f"(c[1]), "+f"(c[2]), "+f"(c[3])
        : "r"(a[0]), "r"(a[1]), "r"(a[2]), "r"(a[3]), "r"(b[0]), "r"(b[1]));
}
__device__ __forceinline__ uint32_t pack_bf16(float x, float y) {
    __nv_bfloat162 t = {__float2bfloat16(x), __float2bfloat16(y)};
    return *reinterpret_cast<uint32_t*>(&t);
}
// swizzled smem addr for GEMM (64B rows, BK=32 bf16)
__device__ __forceinline__ uint32_t swz(uint32_t tb, int row, int kc) {
    return tb + row * 64 + (((kc ^ ((row >> 1) & 3)) & 3) << 4);
}

// ---------------- split fp32 -> bf16 hi/lo ----------------
__global__ __launch_bounds__(256) void split_kernel(
    const float* __restrict__ src, __nv_bfloat16* __restrict__ hi,
    __nv_bfloat16* __restrict__ lo, int n)
{
    int i = (blockIdx.x * 256 + threadIdx.x) * 4;
    if (i < n) {
        float4 x = *(const float4*)(src + i);
        __nv_bfloat16 h0 = __float2bfloat16(x.x);
        __nv_bfloat16 h1 = __float2bfloat16(x.y);
        __nv_bfloat16 h2 = __float2bfloat16(x.z);
        __nv_bfloat16 h3 = __float2bfloat16(x.w);
        __nv_bfloat162 H0 = {h0, h1}, H1 = {h2, h3};
        __nv_bfloat162 L0 = {__float2bfloat16(x.x - __bfloat162float(h0)),
                             __float2bfloat16(x.y - __bfloat162float(h1))};
        __nv_bfloat162 L1 = {__float2bfloat16(x.z - __bfloat162float(h2)),
                             __float2bfloat16(x.w - __bfloat162float(h3))};
        *(__nv_bfloat162*)(hi + i)     = H0;
        *(__nv_bfloat162*)(hi + i + 2) = H1;
        *(__nv_bfloat162*)(lo + i)     = L0;
        *(__nv_bfloat162*)(lo + i + 2) = L1;
    }
}

// ---------------- GEMM core (shared by both kernels) ----------------
// 128x128 CTA tile, BK=32, 8 warps (2x4), warp tile 64x32, 3-stage cp.async,
// one __syncthreads per stage. 3 mma passes (hh, hl, lh).
#define TILE_B 8192
#define STAGE_B (4 * TILE_B)      // 32 KB
#define NSTAGE 3
#define GEMM_SMEM (NSTAGE * STAGE_B)

struct GemmCtx {
    const __nv_bfloat16* gsrc[4];  // Ahi, Alo, Bhi, Blo
    int m0, n0loc, K;
};

__device__ __forceinline__ void gemm_load_stage(
    const GemmCtx& cx, uint32_t sb, int slot, int k0, int tid)
{
#pragma unroll
    for (int t = 0; t < 8; t++) {
        const int tile = t >> 1;
        const int ci = ((t & 1) << 8) + tid;
        const int row = ci >> 2;
        const int c = ci & 3;
        const int r0 = (tile < 2) ? cx.m0 : cx.n0loc;
        const __nv_bfloat16* g = cx.gsrc[tile] + (size_t)(r0 + row) * cx.K + k0 + c * 8;
        cpasync16(swz(sb + slot * STAGE_B + tile * TILE_B, row, c), g);
    }
    asm volatile("cp.async.commit_group;" ::: "memory");
}

__device__ __forceinline__ void gemm_compute_stage(
    uint32_t sb, int slot, int lane, int wm, int wn, float acc[4][4][4])
{
    const uint32_t base = sb + slot * STAGE_B;
    const uint32_t Ahi_b = base, Alo_b = base + TILE_B;
    const uint32_t Bhi_b = base + 2 * TILE_B, Blo_b = base + 3 * TILE_B;
    const int a_row = wm * 64 + (lane & 15);
    const int a_kc = (lane >> 4) & 1;
    const int b_row = wn * 32 + (lane & 7) + ((lane >> 4) & 1) * 8;
    const int b_kc = (lane >> 3) & 1;
#pragma unroll
    for (int k2 = 0; k2 < 2; k2++) {
        const int kcb = k2 * 2;
        uint32_t ahi[4][4], alo[4][4], bhi[2][4], blo[2][4];
#pragma unroll
        for (int mi = 0; mi < 4; mi++) {
            ldsm4(ahi[mi], swz(Ahi_b, a_row + mi * 16, kcb + a_kc));
            ldsm4(alo[mi], swz(Alo_b, a_row + mi * 16, kcb + a_kc));
        }
#pragma unroll
        for (int nj = 0; nj < 2; nj++) {
            ldsm4(bhi[nj], swz(Bhi_b, b_row + nj * 16, kcb + b_kc));
            ldsm4(blo[nj], swz(Blo_b, b_row + nj * 16, kcb + b_kc));
        }
#pragma unroll
        for (int mi = 0; mi < 4; mi++)
#pragma unroll
            for (int ni = 0; ni < 4; ni++) {
                const uint32_t* bh = &bhi[ni >> 1][(ni & 1) * 2];
                const uint32_t* bl = &blo[ni >> 1][(ni & 1) * 2];
                mma_bf16(acc[mi][ni], ahi[mi], bh);
                mma_bf16(acc[mi][ni], ahi[mi], bl);
                mma_bf16(acc[mi][ni], alo[mi], bh);
            }
    }
}

#define GEMM_MAINLOOP(cx)                                                     \
    float acc[4][4][4];                                                       \
    _Pragma("unroll") for (int i = 0; i < 4; i++)                             \
    _Pragma("unroll") for (int j = 0; j < 4; j++)                             \
    _Pragma("unroll") for (int c = 0; c < 4; c++) acc[i][j][c] = 0.0f;        \
    const int KS = (cx).K >> 5;                                               \
    gemm_load_stage(cx, sb, 0, 0, tid);                                       \
    gemm_load_stage(cx, sb, 1, 32, tid);                                      \
    int slot = 0;                                                             \
    for (int s = 0; s < KS; s++) {                                            \
        if (s < KS - 1) { asm volatile("cp.async.wait_group 1;" ::: "memory"); } \
        else            { asm volatile("cp.async.wait_group 0;" ::: "memory"); } \
        __syncthreads();                                                      \
        if (s + 2 < KS) {                                                     \
            int ns = slot + 2; if (ns >= NSTAGE) ns -= NSTAGE;                \
            gemm_load_stage(cx, sb, ns, (s + 2) * 32, tid);                   \
        }                                                                     \
        gemm_compute_stage(sb, slot, lane, wm, wn, acc);                      \
        if (++slot == NSTAGE) slot = 0;                                       \
    }

// ---------------- fused QKV projection (bf16x3, hi/lo split epilogue) ------------
__global__ __launch_bounds__(256, 1) void gemm_qkv(
    const __nv_bfloat16* __restrict__ Xhi, const __nv_bfloat16* __restrict__ Xlo,
    const __nv_bfloat16* __restrict__ qwh, const __nv_bfloat16* __restrict__ qwl,
    const __nv_bfloat16* __restrict__ kwh, const __nv_bfloat16* __restrict__ kwl,
    const __nv_bfloat16* __restrict__ vwh, const __nv_bfloat16* __restrict__ vwl,
    const float* __restrict__ q_b, const float* __restrict__ k_b, const float* __restrict__ v_b,
    __nv_bfloat16* __restrict__ qhi, __nv_bfloat16* __restrict__ qlo,
    __nv_bfloat16* __restrict__ khi, __nv_bfloat16* __restrict__ klo,
    __nv_bfloat16* __restrict__ vhi, __nv_bfloat16* __restrict__ vlo)
{
    extern __shared__ char smraw[];
    const uint32_t sb = smem_u32(smraw);
    const int tid = threadIdx.x, lane = tid & 31, wid = tid >> 5;
    const int wm = wid & 1, wn = wid >> 1;
    const int nt = blockIdx.x;          // 0..23

    const __nv_bfloat16 *Wh, *Wl;
    const float* bias;
    __nv_bfloat16 *Yh, *Yl;
    int Nseg, nloc;
    float oscale;
    if (nt < 16)      { Wh = qwh; Wl = qwl; bias = q_b; Yh = qhi; Yl = qlo;
                        Nseg = HIDDEN; nloc = nt * 128;        oscale = QSCALE; }
    else if (nt < 20) { Wh = kwh; Wl = kwl; bias = k_b; Yh = khi; Yl = klo;
                        Nseg = KVDIM;  nloc = (nt - 16) * 128; oscale = 1.0f; }
    else              { Wh = vwh; Wl = vwl; bias = v_b; Yh = vhi; Yl = vlo;
                        Nseg = KVDIM;  nloc = (nt - 20) * 128; oscale = 1.0f; }

    GemmCtx cx;
    cx.gsrc[0] = Xhi; cx.gsrc[1] = Xlo; cx.gsrc[2] = Wh; cx.gsrc[3] = Wl;
    cx.m0 = blockIdx.y * 128; cx.n0loc = nloc; cx.K = HIDDEN;

    GEMM_MAINLOOP(cx)

#pragma unroll
    for (int mi = 0; mi < 4; mi++) {
        const int r0 = cx.m0 + wm * 64 + mi * 16 + (lane >> 2);
#pragma unroll
        for (int ni = 0; ni < 4; ni++) {
            const int col = nloc + wn * 32 + ni * 8 + (lane & 3) * 2;
            float2 bv = *(const float2*)(bias + col);
            float v0 = (acc[mi][ni][0] + bv.x) * oscale;
            float v1 = (acc[mi][ni][1] + bv.y) * oscale;
            float v2 = (acc[mi][ni][2] + bv.x) * oscale;
            float v3 = (acc[mi][ni][3] + bv.y) * oscale;
            float h0 = __bfloat162float(__float2bfloat16(v0));
            float h1 = __bfloat162float(__float2bfloat16(v1));
            float h2 = __bfloat162float(__float2bfloat16(v2));
            float h3 = __bfloat162float(__float2bfloat16(v3));
            *(uint32_t*)(Yh + (size_t)r0 * Nseg + col)       = pack_bf16(v0, v1);
            *(uint32_t*)(Yl + (size_t)r0 * Nseg + col)       = pack_bf16(v0 - h0, v1 - h1);
            *(uint32_t*)(Yh + (size_t)(r0 + 8) * Nseg + col) = pack_bf16(v2, v3);
            *(uint32_t*)(Yl + (size_t)(r0 + 8) * Nseg + col) = pack_bf16(v2 - h2, v3 - h3);
        }
    }
}

// ---------------- O projection (bf16x3 -> fp32) ----------------
__global__ __launch_bounds__(256, 1) void gemm_oproj(
    const __nv_bfloat16* __restrict__ Xhi, const __nv_bfloat16* __restrict__ Xlo,
    const __nv_bfloat16* __restrict__ Whi, const __nv_bfloat16* __restrict__ Wlo,
    const float* __restrict__ bias, float* __restrict__ Y, int N, int K)
{
    extern __shared__ char smraw[];
    const uint32_t sb = smem_u32(smraw);
    const int tid = threadIdx.x, lane = tid & 31, wid = tid >> 5;
    const int wm = wid & 1, wn = wid >> 1;

    GemmCtx cx;
    cx.gsrc[0] = Xhi; cx.gsrc[1] = Xlo; cx.gsrc[2] = Whi; cx.gsrc[3] = Wlo;
    cx.m0 = blockIdx.y * 128; cx.n0loc = blockIdx.x * 128; cx.K = K;

    GEMM_MAINLOOP(cx)

#pragma unroll
    for (int mi = 0; mi < 4; mi++) {
        const int r0 = cx.m0 + wm * 64 + mi * 16 + (lane >> 2);
#pragma unroll
        for (int ni = 0; ni < 4; ni++) {
            const int col = cx.n0loc + wn * 32 + ni * 8 + (lane & 3) * 2;
            float2 bv = *(const float2*)(bias + col);
            float2 v0 = {acc[mi][ni][0] + bv.x, acc[mi][ni][1] + bv.y};
            float2 v1 = {acc[mi][ni][2] + bv.x, acc[mi][ni][3] + bv.y};
            *(float2*)(Y + (size_t)r0 * N + col) = v0;
            *(float2*)(Y + (size_t)(r0 + 8) * N + col) = v1;
        }
    }
}

// ---------------- tensor-core flash attention (bf16x3, causal + pad mask) --------
#define KV_PLANE 9216          // 64 rows * 144B
#define KV_BUF   (4 * KV_PLANE)
#define MS_OFF   (2 * KV_BUF)  // 73728
#define FLASH_SMEM (MS_OFF + 512)

__global__ __launch_bounds__(256, 1) void flash_tc(
    const __nv_bfloat16* __restrict__ Qhi, const __nv_bfloat16* __restrict__ Qlo,
    const __nv_bfloat16* __restrict__ Khi, const __nv_bfloat16* __restrict__ Klo,
    const __nv_bfloat16* __restrict__ Vhi, const __nv_bfloat16* __restrict__ Vlo,
    const int* __restrict__ AM,
    __nv_bfloat16* __restrict__ Ohi, __nv_bfloat16* __restrict__ Olo)
{
    extern __shared__ char smraw[];
    const uint32_t sb = smem_u32(smraw);
    const int tid = threadIdx.x, lane = tid & 31, w = tid >> 5;
    const int qb = blockIdx.x, h = blockIdx.y, b = blockIdx.z;
    const int kvh = h >> 2;
    const int rbase = qb * 128 + w * 16;
    const int g = lane >> 2;
    const int qd = lane & 3;

#pragma unroll
    for (int j = 0; j < 8; j++) {
        int c = tid + j * 256;
        int pl = c >> 10, row = (c >> 3) & 127, ch = c & 7;
        const __nv_bfloat16* src = (pl ? Qlo : Qhi)
            + ((size_t)(b * LQ + qb * 128 + row) * NQH + h) * HDIM + ch * 8;
        cpasync16(sb + pl * 18432 + row * 144 + ch * 16, src);
    }
    asm volatile("cp.async.commit_group;" ::: "memory");
    asm volatile("cp.async.wait_group 0;" ::: "memory");
    __syncthreads();

    uint32_t qh[4][4], ql[4][4];
#pragma unroll
    for (int kt = 0; kt < 4; kt++) {
        uint32_t off = (uint32_t)((w * 16 + (lane & 15)) * 144 + kt * 32 + ((lane >> 4) & 1) * 16);
        ldsm4(qh[kt], sb + off);
        ldsm4(ql[kt], sb + 18432 + off);
    }
    __syncthreads();

    const __nv_bfloat16* kvsrc[4] = {Khi, Klo, Vhi, Vlo};
    auto load_kv = [&](int buf, int t0) {
#pragma unroll
        for (int j = 0; j < 8; j++) {
            int c = tid + j * 256;
            int pl = c >> 9, row = (c >> 3) & 63, ch = c & 7;
            const __nv_bfloat16* src = kvsrc[pl]
                + ((size_t)(b * LQ + t0 + row) * NKVH + kvh) * HDIM + ch * 8;
            cpasync16(sb + buf * KV_BUF + pl * KV_PLANE + row * 144 + ch * 16, src);
        }
        if (tid < 16)
            cpasync16(sb + MS_OFF + buf * 256 + tid * 16, AM + (size_t)b * LQ + t0 + tid * 4);
        asm volatile("cp.async.commit_group;" ::: "memory");
    };

    const int NI = 2 * qb + 2;
    load_kv(0, 0);
    if (NI > 1) load_kv(1, 64);

    float m0 = -1e30f, m1 = -1e30f, l0 = 0.0f, l1 = 0.0f;
    float o[8][4];
#pragma unroll
    for (int i = 0; i < 8; i++)
#pragma unroll
        for (int c = 0; c < 4; c++) o[i][c] = 0.0f;

    for (int it = 0; it < NI; it++) {
        if (it + 1 < NI) {
            asm volatile("cp.async.wait_group 1;" ::: "memory");
        } else {
            asm volatile("cp.async.wait_group 0;" ::: "memory");
        }
        __syncthreads();
        const int buf = it & 1;
        const int t0 = it * 64;
        const uint32_t kvb = sb + buf * KV_BUF;
        const int* Ms = (const int*)(smraw + MS_OFF + buf * 256);

        float sc[8][4];
#pragma unroll
        for (int i = 0; i < 8; i++)
#pragma unroll
            for (int c = 0; c < 4; c++) sc[i][c] = 0.0f;

#pragma unroll
        for (int kt = 0; kt < 4; kt++) {
            uint32_t bh[4][4], bl[4][4];
#pragma unroll
            for (int ng = 0; ng < 4; ng++) {
                uint32_t off = (uint32_t)((ng * 16 + (lane & 15)) * 144 + kt * 32 + ((lane >> 4) & 1) * 16);
                ldsm4(bh[ng], kvb + off);
                ldsm4(bl[ng], kvb + KV_PLANE + off);
            }
#pragma unroll
            for (int ng = 0; ng < 4; ng++)
#pragma unroll
                for (int hh = 0; hh < 2; hh++) {
                    uint32_t fh[2] = {bh[ng][hh], bh[ng][hh + 2]};
                    uint32_t fl[2] = {bl[ng][hh], bl[ng][hh + 2]};
                    mma_bf16(sc[2 * ng + hh], qh[kt], fh);
                    mma_bf16(sc[2 * ng + hh], qh[kt], fl);
                    mma_bf16(sc[2 * ng + hh], ql[kt], fh);
                }
        }

        const int rowA = rbase + g, rowB = rowA + 8;
        const bool needc = (t0 + 63 > rbase);
#pragma unroll
        for (int ni = 0; ni < 8; ni++) {
            int c0 = ni * 8 + qd * 2, c1 = c0 + 1;
            bool v0 = (Ms[c0] != 0), v1 = (Ms[c1] != 0);
            int g0 = t0 + c0, g1 = t0 + c1;
            if (!v0 || (needc && g0 > rowA)) sc[ni][0] = -1e30f;
            if (!v1 || (needc && g1 > rowA)) sc[ni][1] = -1e30f;
            if (!v0 || (needc && g0 > rowB)) sc[ni][2] = -1e30f;
            if (!v1 || (needc && g1 > rowB)) sc[ni][3] = -1e30f;
        }

        float mn0 = m0, mn1 = m1;
#pragma unroll
        for (int ni = 0; ni < 8; ni++) {
            mn0 = fmaxf(mn0, fmaxf(sc[ni][0], sc[ni][1]));
            mn1 = fmaxf(mn1, fmaxf(sc[ni][2], sc[ni][3]));
        }
        mn0 = fmaxf(mn0, __shfl_xor_sync(0xffffffffu, mn0, 1));
        mn0 = fmaxf(mn0, __shfl_xor_sync(0xffffffffu, mn0, 2));
        mn1 = fmaxf(mn1, __shfl_xor_sync(0xffffffffu, mn1, 1));
        mn1 = fmaxf(mn1, __shfl_xor_sync(0xffffffffu, mn1, 2));
        float s0 = exp2f(m0 - mn0), s1 = exp2f(m1 - mn1);
        float rs0 = 0.0f, rs1 = 0.0f;
#pragma unroll
        for (int ni = 0; ni < 8; ni++) {
            sc[ni][0] = exp2f(sc[ni][0] - mn0);
            sc[ni][1] = exp2f(sc[ni][1] - mn0);
            sc[ni][2] = exp2f(sc[ni][2] - mn1);
            sc[ni][3] = exp2f(sc[ni][3] - mn1);
            rs0 += sc[ni][0] + sc[ni][1];
            rs1 += sc[ni][2] + sc[ni][3];
        }
        rs0 += __shfl_xor_sync(0xffffffffu, rs0, 1);
        rs0 += __shfl_xor_sync(0xffffffffu, rs0, 2);
        rs1 += __shfl_xor_sync(0xffffffffu, rs1, 1);
        rs1 += __shfl_xor_sync(0xffffffffu, rs1, 2);
        l0 = l0 * s0 + rs0;
        l1 = l1 * s1 + rs1;
        m0 = mn0; m1 = mn1;
#pragma unroll
        for (int ni = 0; ni < 8; ni++) {
            o[ni][0] *= s0; o[ni][1] *= s0;
            o[ni][2] *= s1; o[ni][3] *= s1;
        }

        uint32_t ph[4][4], pl[4][4];
#pragma unroll
        for (int kt = 0; kt < 4; kt++)
#pragma unroll
            for (int j = 0; j < 4; j++) {
                int ni = 2 * kt + (j >> 1);
                int e = (j & 1) * 2;
                float x0 = sc[ni][e], x1 = sc[ni][e + 1];
                float h0 = __bfloat162float(__float2bfloat16(x0));
                float h1 = __bfloat162float(__float2bfloat16(x1));
                ph[kt][j] = pack_bf16(x0, x1);
                pl[kt][j] = pack_bf16(x0 - h0, x1 - h1);
            }

#pragma unroll
        for (int kt = 0; kt < 4; kt++)
#pragma unroll
            for (int dg = 0; dg < 4; dg++) {
                uint32_t vh[4], vl[4];
                uint32_t off = (uint32_t)((kt * 16 + (lane & 15)) * 144 + dg * 32 + ((lane >> 4) & 1) * 16);
                ldsm4t(vh, kvb + 2 * KV_PLANE + off);
                ldsm4t(vl, kvb + 3 * KV_PLANE + off);
                mma_bf16(o[2 * dg],     ph[kt], &vh[0]);
                mma_bf16(o[2 * dg],     ph[kt], &vl[0]);
                mma_bf16(o[2 * dg],     pl[kt], &vh[0]);
                mma_bf16(o[2 * dg + 1], ph[kt], &vh[2]);
                mma_bf16(o[2 * dg + 1], ph[kt], &vl[2]);
                mma_bf16(o[2 * dg + 1], pl[kt], &vh[2]);
            }

        __syncthreads();
        if (it + 2 < NI) load_kv(buf, (it + 2) * 64);
    }

    const float inv0 = 1.0f / l0, inv1 = 1.0f / l1;
    const int rowA = rbase + g;
#pragma unroll
    for (int ni = 0; ni < 8; ni++) {
        int col = ni * 8 + qd * 2;
        float a0 = o[ni][0] * inv0, a1 = o[ni][1] * inv0;
        float b0 = o[ni][2] * inv1, b1 = o[ni][3] * inv1;
        float h0 = __bfloat162float(__float2bfloat16(a0));
        float h1 = __bfloat162float(__float2bfloat16(a1));
        float h2 = __bfloat162float(__float2bfloat16(b0));
        float h3 = __bfloat162float(__float2bfloat16(b1));
        size_t baseA = ((size_t)(b * LQ + rowA) * NQH + h) * HDIM + col;
        size_t baseB = ((size_t)(b * LQ + rowA + 8) * NQH + h) * HDIM + col;
        *(uint32_t*)(Ohi + baseA) = pack_bf16(a0, a1);
        *(uint32_t*)(Olo + baseA) = pack_bf16(a0 - h0, a1 - h1);
        *(uint32_t*)(Ohi + baseB) = pack_bf16(b0, b1);
        *(uint32_t*)(Olo + baseB) = pack_bf16(b0 - h2, b1 - h3);
    }
}

// ---------------- launch ----------------
extern "C" void kernel_launch(void* const* d_in, const int* in_sizes, int n_in,
                              void* d_out, int out_size)
{
    const float* x   = (const float*)d_in[0];
    const int*   am  = (const int*)  d_in[1];
    const float* q_w = (const float*)d_in[2];
    const float* q_b = (const float*)d_in[3];
    const float* k_w = (const float*)d_in[4];
    const float* k_b = (const float*)d_in[5];
    const float* v_w = (const float*)d_in[6];
    const float* v_b = (const float*)d_in[7];
    const float* o_w = (const float*)d_in[8];
    const float* o_b = (const float*)d_in[9];
    float* out = (float*)d_out;

    __nv_bfloat16 *xhi, *xlo, *qwh, *qwl, *kwh, *kwl, *vwh, *vwl, *owh, *owl;
    __nv_bfloat16 *qhi, *qlo, *khi, *klo, *vhi, *vlo, *ahi, *alo;
    cudaGetSymbolAddress((void**)&xhi, g_xhi);  cudaGetSymbolAddress((void**)&xlo, g_xlo);
    cudaGetSymbolAddress((void**)&qwh, g_qwhi); cudaGetSymbolAddress((void**)&qwl, g_qwlo);
    cudaGetSymbolAddress((void**)&kwh, g_kwhi); cudaGetSymbolAddress((void**)&kwl, g_kwlo);
    cudaGetSymbolAddress((void**)&vwh, g_vwhi); cudaGetSymbolAddress((void**)&vwl, g_vwlo);
    cudaGetSymbolAddress((void**)&owh, g_owhi); cudaGetSymbolAddress((void**)&owl, g_owlo);
    cudaGetSymbolAddress((void**)&qhi, g_qhi);  cudaGetSymbolAddress((void**)&qlo, g_qlo);
    cudaGetSymbolAddress((void**)&khi, g_khi);  cudaGetSymbolAddress((void**)&klo, g_klo);
    cudaGetSymbolAddress((void**)&vhi, g_vhi);  cudaGetSymbolAddress((void**)&vlo, g_vlo);
    cudaGetSymbolAddress((void**)&ahi, g_ahi);  cudaGetSymbolAddress((void**)&alo, g_alo);

    static bool attr_done = false;
    if (!attr_done) {
        cudaFuncSetAttribute(gemm_qkv,   cudaFuncAttributeMaxDynamicSharedMemorySize, GEMM_SMEM);
        cudaFuncSetAttribute(gemm_oproj, cudaFuncAttributeMaxDynamicSharedMemorySize, GEMM_SMEM);
        cudaFuncSetAttribute(flash_tc,   cudaFuncAttributeMaxDynamicSharedMemorySize, FLASH_SMEM);
        attr_done = true;
    }

    auto split = [](const float* s, __nv_bfloat16* h, __nv_bfloat16* l, int n) {
        split_kernel<<<(n / 4 + 255) / 256, 256>>>(s, h, l, n);
    };
    split(x, xhi, xlo, MROWS * HIDDEN);
    split(q_w, qwh, qwl, HIDDEN * HIDDEN);
    split(k_w, kwh, kwl, KVDIM * HIDDEN);
    split(v_w, vwh, vwl, KVDIM * HIDDEN);
    split(o_w, owh, owl, HIDDEN * HIDDEN);

    // fused Q/K/V projection (Q gets softmax scale folded in)
    gemm_qkv<<<dim3(24, MROWS / 128), 256, GEMM_SMEM>>>(
        xhi, xlo, qwh, qwl, kwh, kwl, vwh, vwl, q_b, k_b, v_b,
        qhi, qlo, khi, klo, vhi, vlo);

    // tensor-core flash attention -> hi/lo planes
    flash_tc<<<dim3(LQ / 128, NQH, BATCH), 256, FLASH_SMEM>>>(
        qhi, qlo, khi, klo, vhi, vlo, am, ahi, alo);

    // output projection -> fp32
    gemm_oproj<<<dim3(HIDDEN / 128, MROWS / 128), 256, GEMM_SMEM>>>(
        ahi, alo, owh, owl, o_b, out, HIDDEN, HIDDEN);
}